// round 2
// baseline (speedup 1.0000x reference)
#include <cuda_runtime.h>

// InverseHaarTransform: fused bilinear-2x upsample + pad(1 top/left) + 2x2 depthwise
// conv + 4-band sum, exploiting rank-1 (separable) structure of the 2x2 filters.
//
// Derivation (half-pixel bilinear 2x, jax edge renormalization == index clamp):
//   up[2i]   = 0.25*x[clamp(i-1)] + 0.75*x[i]
//   up[2i+1] = 0.75*x[i]          + 0.25*x[clamp(i+1)]
// out[y][x] = f00*U[y-1][x-1] + f01*U[y-1][x] + f10*U[y][x-1] + f11*U[y][x]
// with U = up zero-extended at row/col -1 (the pad).
// If f = col (x) row (rank-1; true for all Haar bands), this factors into a
// vertical stage T (per input column) followed by a horizontal stage:
//   even out-row 2i:   T_ev[j] = e0*x[i-1][j] + e1*x[i][j]      (e0=0, e1=c1 at i==0)
//   odd  out-row 2i+1: T_od[j] = o0*x[i-1][j] + o1*x[i][j] + o2*x[i+1][j]
//   even out-col 2j:   E0*T[j-1] + E1*T[j]                      (E0=0, E1=r1 at j==0)
//   odd  out-col 2j+1: O0*T[j-1] + O1*T[j] + O2*T[j+1]
// Rank-1 factors are computed at runtime from the filter inputs.

#define CW 8  // input columns per thread -> 2x16 output block per thread

__global__ void __launch_bounds__(256) ihaar_kernel(
    const float* __restrict__ x,
    const float* __restrict__ f0p, const float* __restrict__ f1p,
    const float* __restrict__ f2p, const float* __restrict__ f3p,
    float* __restrict__ out)
{
    const int tid = blockIdx.x * 256 + threadIdx.x;
    const int g  = tid & 63;            // column group: 512 / CW = 64
    const int i  = (tid >> 6) & 511;    // input row
    const int bc = tid >> 15;           // b*3 + c, 0..47

    const int W = 512;
    const size_t HW = (size_t)512 * 512;
    const int b = bc / 3, c = bc - 3 * b;
    const float* xb = x + (size_t)b * 12 * HW + (size_t)c * HW;

    const int j0 = g * CW;
    const int im = (i > 0)   ? i - 1 : 0;
    const int ip = (i < 511) ? i + 1 : 511;
    const bool top  = (i == 0);
    const bool left = (g == 0);
    const int jl = left ? 0 : j0 - 1;
    const int jr = (g == 63) ? 511 : j0 + CW;

    float acc0[2 * CW], acc1[2 * CW];
#pragma unroll
    for (int t = 0; t < 2 * CW; ++t) { acc0[t] = 0.0f; acc1[t] = 0.0f; }

    const float* fp[4] = { f0p, f1p, f2p, f3p };

#pragma unroll
    for (int k = 0; k < 4; ++k) {
        const float* ch = xb + (size_t)(3 * k) * HW;   // channel c + 3k
        const float* rm = ch + (size_t)im * W;
        const float* rc = ch + (size_t)i  * W;
        const float* rp = ch + (size_t)ip * W;

        // Load 3 rows x (CW+2) cols (clamped halo)
        float xm[CW + 2], x0[CW + 2], xp[CW + 2];
        xm[0] = __ldg(rm + jl); x0[0] = __ldg(rc + jl); xp[0] = __ldg(rp + jl);
#pragma unroll
        for (int t = 0; t < CW; t += 4) {
            float4 a  = *(const float4*)(rm + j0 + t);
            xm[1 + t] = a.x;  xm[2 + t] = a.y;  xm[3 + t] = a.z;  xm[4 + t] = a.w;
            float4 bb = *(const float4*)(rc + j0 + t);
            x0[1 + t] = bb.x; x0[2 + t] = bb.y; x0[3 + t] = bb.z; x0[4 + t] = bb.w;
            float4 cc = *(const float4*)(rp + j0 + t);
            xp[1 + t] = cc.x; xp[2 + t] = cc.y; xp[3 + t] = cc.z; xp[4 + t] = cc.w;
        }
        xm[CW + 1] = __ldg(rm + jr); x0[CW + 1] = __ldg(rc + jr); xp[CW + 1] = __ldg(rp + jr);

        // Rank-1 factorization of this band's 2x2 filter (from input data)
        const float f00 = __ldg(fp[k] + 0), f01 = __ldg(fp[k] + 1);
        const float f10 = __ldg(fp[k] + 2), f11 = __ldg(fp[k] + 3);
        float r0, r1, c0, c1;
        if (f00 != 0.0f) { r0 = f00; r1 = f01; c0 = 1.0f; c1 = f10 / f00; }
        else             { r0 = f10; r1 = f11; c0 = 0.0f; c1 = 1.0f; }

        const float e0 = top ? 0.0f : (0.75f * c0 + 0.25f * c1);
        const float e1 = top ? c1   : (0.25f * c0 + 0.75f * c1);
        const float o0 = 0.25f * c0, o1 = 0.75f * (c0 + c1), o2 = 0.25f * c1;
        const float E0 = 0.75f * r0 + 0.25f * r1;
        const float E1 = 0.25f * r0 + 0.75f * r1;
        const float E0f = left ? 0.0f : E0;    // x==0 hits the left zero-pad
        const float E1f = left ? r1   : E1;
        const float O0 = 0.25f * r0, O1 = 0.75f * (r0 + r1), O2 = 0.25f * r1;

        // Vertical stage
        float Tev[CW + 2], Tod[CW + 2];
#pragma unroll
        for (int t = 0; t < CW + 2; ++t) {
            Tev[t] = e0 * xm[t] + e1 * x0[t];
            Tod[t] = o0 * xm[t] + o1 * x0[t] + o2 * xp[t];
        }

        // Horizontal stage + band accumulation
#pragma unroll
        for (int jj = 0; jj < CW; ++jj) {
            const float we0 = (jj == 0) ? E0f : E0;
            const float we1 = (jj == 0) ? E1f : E1;
            acc0[2 * jj]     += we0 * Tev[jj] + we1 * Tev[jj + 1];
            acc1[2 * jj]     += we0 * Tod[jj] + we1 * Tod[jj + 1];
            acc0[2 * jj + 1] += O0 * Tev[jj] + O1 * Tev[jj + 1] + O2 * Tev[jj + 2];
            acc1[2 * jj + 1] += O0 * Tod[jj] + O1 * Tod[jj + 1] + O2 * Tod[jj + 2];
        }
    }

    float* ob0 = out + ((size_t)bc * 1024 + (size_t)(2 * i)) * 1024 + (size_t)(2 * j0);
    float* ob1 = ob0 + 1024;
#pragma unroll
    for (int t = 0; t < 2 * CW; t += 4) {
        *(float4*)(ob0 + t) = make_float4(acc0[t], acc0[t + 1], acc0[t + 2], acc0[t + 3]);
        *(float4*)(ob1 + t) = make_float4(acc1[t], acc1[t + 1], acc1[t + 2], acc1[t + 3]);
    }
}

extern "C" void kernel_launch(void* const* d_in, const int* in_sizes, int n_in,
                              void* d_out, int out_size) {
    const float* x = (const float*)d_in[0];
    // inputs (metadata order): x, fll, flh, fhl, fhh
    const int total = 48 * 512 * 64;   // (16*3) channels x 512 rows x 64 col-groups
    ihaar_kernel<<<total / 256, 256>>>(
        x,
        (const float*)d_in[1], (const float*)d_in[2],
        (const float*)d_in[3], (const float*)d_in[4],
        (float*)d_out);
}

// round 4
// speedup vs baseline: 1.1205x; 1.1205x over previous
#include <cuda_runtime.h>

// InverseHaarTransform: fused bilinear-2x upsample + pad(1 top/left) + 2x2 depthwise
// conv + 4-band sum, exploiting rank-1 (separable) structure of the 2x2 filters.
//
//   up[2i]   = 0.25*x[clamp(i-1)] + 0.75*x[i]
//   up[2i+1] = 0.75*x[i]          + 0.25*x[clamp(i+1)]
// out = 2x2 FIR over zero-padded (1 top, 1 left) upsampled image; each Haar
// filter is rank-1 -> separable vertical (e/o taps) then horizontal (E/O taps).
//
// R2 change vs R1: halo values come from warp shuffles (neighbor lanes hold
// them as vector-load elements) instead of scattered scalar LDGs, which were
// ~60% of L1 wavefronts. Only warp-boundary lanes do a predicated 1-sector
// load; image edges clamp to the lane's own element. Plus launch_bounds min
// 3 CTAs/SM for occupancy.

#define CW 8  // input columns per thread -> 2x16 output block per thread

__device__ __forceinline__ void load_row(const float* __restrict__ r, int j0,
                                         int lane, bool img_left, bool img_right,
                                         float v[CW + 2])
{
    float4 a = *(const float4*)(r + j0);
    float4 b = *(const float4*)(r + j0 + 4);
    v[1] = a.x; v[2] = a.y; v[3] = a.z; v[4] = a.w;
    v[5] = b.x; v[6] = b.y; v[7] = b.z; v[8] = b.w;
    // halos from neighbor lanes (g is lane-consecutive within a warp)
    float left  = __shfl_up_sync(0xffffffffu, v[8], 1);
    float right = __shfl_down_sync(0xffffffffu, v[1], 1);
    if (lane == 0)  left  = img_left  ? v[1] : __ldg(r + j0 - 1);   // cross-warp seam
    if (lane == 31) right = img_right ? v[8] : __ldg(r + j0 + CW);
    v[0] = left; v[CW + 1] = right;
}

__global__ void __launch_bounds__(256, 3) ihaar_kernel(
    const float* __restrict__ x,
    const float* __restrict__ f0p, const float* __restrict__ f1p,
    const float* __restrict__ f2p, const float* __restrict__ f3p,
    float* __restrict__ out)
{
    const int tid = blockIdx.x * 256 + threadIdx.x;
    const int g  = tid & 63;            // column group: 512 / CW = 64
    const int i  = (tid >> 6) & 511;    // input row
    const int bc = tid >> 15;           // b*3 + c, 0..47
    const int lane = threadIdx.x & 31;

    const int W = 512;
    const size_t HW = (size_t)512 * 512;
    const int b = bc / 3, c = bc - 3 * b;
    const float* xb = x + (size_t)b * 12 * HW + (size_t)c * HW;

    const int j0 = g * CW;
    const int im = (i > 0)   ? i - 1 : 0;
    const int ip = (i < 511) ? i + 1 : 511;
    const bool top       = (i == 0);
    const bool img_left  = (g == 0);
    const bool img_right = (g == 63);

    float acc0[2 * CW], acc1[2 * CW];
#pragma unroll
    for (int t = 0; t < 2 * CW; ++t) { acc0[t] = 0.0f; acc1[t] = 0.0f; }

    const float* fp[4] = { f0p, f1p, f2p, f3p };

#pragma unroll
    for (int k = 0; k < 4; ++k) {
        const float* ch = xb + (size_t)(3 * k) * HW;   // channel c + 3k
        float xm[CW + 2], x0[CW + 2], xp[CW + 2];
        load_row(ch + (size_t)im * W, j0, lane, img_left, img_right, xm);
        load_row(ch + (size_t)i  * W, j0, lane, img_left, img_right, x0);
        load_row(ch + (size_t)ip * W, j0, lane, img_left, img_right, xp);

        // Rank-1 factorization of this band's 2x2 filter (from input data)
        const float f00 = __ldg(fp[k] + 0), f01 = __ldg(fp[k] + 1);
        const float f10 = __ldg(fp[k] + 2), f11 = __ldg(fp[k] + 3);
        float r0, r1, c0, c1;
        if (f00 != 0.0f) { r0 = f00; r1 = f01; c0 = 1.0f; c1 = f10 / f00; }
        else             { r0 = f10; r1 = f11; c0 = 0.0f; c1 = 1.0f; }

        const float e0 = top ? 0.0f : (0.75f * c0 + 0.25f * c1);
        const float e1 = top ? c1   : (0.25f * c0 + 0.75f * c1);
        const float o0 = 0.25f * c0, o1 = 0.75f * (c0 + c1), o2 = 0.25f * c1;
        const float E0 = 0.75f * r0 + 0.25f * r1;
        const float E1 = 0.25f * r0 + 0.75f * r1;
        const float E0f = img_left ? 0.0f : E0;    // x==0 hits the left zero-pad
        const float E1f = img_left ? r1   : E1;
        const float O0 = 0.25f * r0, O1 = 0.75f * (r0 + r1), O2 = 0.25f * r1;

        // Vertical stage
        float Tev[CW + 2], Tod[CW + 2];
#pragma unroll
        for (int t = 0; t < CW + 2; ++t) {
            Tev[t] = e0 * xm[t] + e1 * x0[t];
            Tod[t] = o0 * xm[t] + o1 * x0[t] + o2 * xp[t];
        }

        // Horizontal stage + band accumulation
#pragma unroll
        for (int jj = 0; jj < CW; ++jj) {
            const float we0 = (jj == 0) ? E0f : E0;
            const float we1 = (jj == 0) ? E1f : E1;
            acc0[2 * jj]     += we0 * Tev[jj] + we1 * Tev[jj + 1];
            acc1[2 * jj]     += we0 * Tod[jj] + we1 * Tod[jj + 1];
            acc0[2 * jj + 1] += O0 * Tev[jj] + O1 * Tev[jj + 1] + O2 * Tev[jj + 2];
            acc1[2 * jj + 1] += O0 * Tod[jj] + O1 * Tod[jj + 1] + O2 * Tod[jj + 2];
        }
    }

    float* ob0 = out + ((size_t)bc * 1024 + (size_t)(2 * i)) * 1024 + (size_t)(2 * j0);
    float* ob1 = ob0 + 1024;
#pragma unroll
    for (int t = 0; t < 2 * CW; t += 4) {
        *(float4*)(ob0 + t) = make_float4(acc0[t], acc0[t + 1], acc0[t + 2], acc0[t + 3]);
        *(float4*)(ob1 + t) = make_float4(acc1[t], acc1[t + 1], acc1[t + 2], acc1[t + 3]);
    }
}

extern "C" void kernel_launch(void* const* d_in, const int* in_sizes, int n_in,
                              void* d_out, int out_size) {
    const float* x = (const float*)d_in[0];
    // inputs (metadata order): x, fll, flh, fhl, fhh
    const int total = 48 * 512 * 64;   // (16*3) channels x 512 rows x 64 col-groups
    ihaar_kernel<<<total / 256, 256>>>(
        x,
        (const float*)d_in[1], (const float*)d_in[2],
        (const float*)d_in[3], (const float*)d_in[4],
        (float*)d_out);
}

// round 5
// speedup vs baseline: 1.2204x; 1.0891x over previous
#include <cuda_runtime.h>

// InverseHaarTransform: fused bilinear-2x upsample + pad(1 top/left) + 2x2 depthwise
// conv + 4-band sum. Each 2x2 Haar filter is rank-1 -> separable vertical then
// horizontal stages:
//   up[2i]   = 0.25*x[clamp(i-1)] + 0.75*x[i]
//   up[2i+1] = 0.75*x[i]          + 0.25*x[clamp(i+1)]
// R4 changes: per-band tap coefficients precomputed by a setup kernel and staged
// into __constant__ memory (FFMA const-bank operands, zero persistent registers),
// top-row handled by warp-uniform branch, 128-thread blocks for finer occupancy
// packing. Halos still via warp shuffle (R2).

#define CW 8  // input columns per thread -> 2x16 output block per thread

// Per band (12 floats): e0,e1,o0,o1,o2, E0,E1,O0,O1,O2, e1t(=c1 for top row), r1(left-edge even col)
__device__   float g_coef_d[48];
__constant__ float g_coef_c[48];

__global__ void ihaar_setup(const float* __restrict__ f0p, const float* __restrict__ f1p,
                            const float* __restrict__ f2p, const float* __restrict__ f3p)
{
    int k = threadIdx.x;
    if (k >= 4) return;
    const float* fp = (k == 0) ? f0p : (k == 1) ? f1p : (k == 2) ? f2p : f3p;
    const float f00 = fp[0], f01 = fp[1], f10 = fp[2], f11 = fp[3];
    float r0, r1, c0, c1;
    if (f00 != 0.0f) { r0 = f00; r1 = f01; c0 = 1.0f; c1 = f10 / f00; }
    else             { r0 = f10; r1 = f11; c0 = 0.0f; c1 = 1.0f; }
    float* o = g_coef_d + 12 * k;
    o[0]  = 0.75f * c0 + 0.25f * c1;   // e0
    o[1]  = 0.25f * c0 + 0.75f * c1;   // e1
    o[2]  = 0.25f * c0;                // o0
    o[3]  = 0.75f * (c0 + c1);         // o1
    o[4]  = 0.25f * c1;                // o2
    o[5]  = 0.75f * r0 + 0.25f * r1;   // E0
    o[6]  = 0.25f * r0 + 0.75f * r1;   // E1
    o[7]  = 0.25f * r0;                // O0
    o[8]  = 0.75f * (r0 + r1);         // O1
    o[9]  = 0.25f * r1;                // O2
    o[10] = c1;                        // e1t (top row: e0t=0, e1t=c1)
    o[11] = r1;                        // left edge even col: out = r1*T[0]
}

__device__ __forceinline__ void load_row(const float* __restrict__ r, int j0,
                                         int lane, bool img_left, bool img_right,
                                         float v[CW + 2])
{
    float4 a = *(const float4*)(r + j0);
    float4 b = *(const float4*)(r + j0 + 4);
    v[1] = a.x; v[2] = a.y; v[3] = a.z; v[4] = a.w;
    v[5] = b.x; v[6] = b.y; v[7] = b.z; v[8] = b.w;
    // halos from neighbor lanes (g is lane-consecutive within a warp)
    float left  = __shfl_up_sync(0xffffffffu, v[8], 1);
    float right = __shfl_down_sync(0xffffffffu, v[1], 1);
    if (lane == 0)  left  = img_left  ? v[1] : __ldg(r + j0 - 1);   // cross-warp seam
    if (lane == 31) right = img_right ? v[8] : __ldg(r + j0 + CW);
    v[0] = left; v[CW + 1] = right;
}

__global__ void __launch_bounds__(128, 6) ihaar_kernel(
    const float* __restrict__ x, float* __restrict__ out)
{
    const int tid = blockIdx.x * 128 + threadIdx.x;
    const int g  = tid & 63;            // column group: 512 / CW = 64
    const int i  = (tid >> 6) & 511;    // input row
    const int bc = tid >> 15;           // b*3 + c, 0..47
    const int lane = threadIdx.x & 31;

    const int W = 512;
    const size_t HW = (size_t)512 * 512;
    const int b = bc / 3, c = bc - 3 * b;
    const float* xb = x + (size_t)b * 12 * HW + (size_t)c * HW;

    const int j0 = g * CW;
    const int im = (i > 0)   ? i - 1 : 0;
    const int ip = (i < 511) ? i + 1 : 511;
    const bool top       = (i == 0);    // warp-uniform
    const bool img_left  = (g == 0);
    const bool img_right = (g == 63);

    float acc0[2 * CW], acc1[2 * CW];
#pragma unroll
    for (int t = 0; t < 2 * CW; ++t) { acc0[t] = 0.0f; acc1[t] = 0.0f; }

#pragma unroll
    for (int k = 0; k < 4; ++k) {
        const float* ch = xb + (size_t)(3 * k) * HW;   // channel c + 3k
        float xm[CW + 2], x0[CW + 2], xp[CW + 2];
        load_row(ch + (size_t)im * W, j0, lane, img_left, img_right, xm);
        load_row(ch + (size_t)i  * W, j0, lane, img_left, img_right, x0);
        load_row(ch + (size_t)ip * W, j0, lane, img_left, img_right, xp);

        const float* C = g_coef_c + 12 * k;   // const-bank operands

        // Vertical stage (top row: e0=0, e1=c1 -> warp-uniform branch)
        float Tev[CW + 2], Tod[CW + 2];
        if (top) {
#pragma unroll
            for (int t = 0; t < CW + 2; ++t) {
                Tev[t] = C[10] * x0[t];
                Tod[t] = C[2] * xm[t] + C[3] * x0[t] + C[4] * xp[t];
            }
        } else {
#pragma unroll
            for (int t = 0; t < CW + 2; ++t) {
                Tev[t] = C[0] * xm[t] + C[1] * x0[t];
                Tod[t] = C[2] * xm[t] + C[3] * x0[t] + C[4] * xp[t];
            }
        }

        // Horizontal stage + band accumulation
        const float we0 = img_left ? 0.0f  : C[5];   // even col jj==0 (left zero-pad)
        const float we1 = img_left ? C[11] : C[6];
        acc0[0] += we0 * Tev[0] + we1 * Tev[1];
        acc1[0] += we0 * Tod[0] + we1 * Tod[1];
        acc0[1] += C[7] * Tev[0] + C[8] * Tev[1] + C[9] * Tev[2];
        acc1[1] += C[7] * Tod[0] + C[8] * Tod[1] + C[9] * Tod[2];
#pragma unroll
        for (int jj = 1; jj < CW; ++jj) {
            acc0[2 * jj]     += C[5] * Tev[jj] + C[6] * Tev[jj + 1];
            acc1[2 * jj]     += C[5] * Tod[jj] + C[6] * Tod[jj + 1];
            acc0[2 * jj + 1] += C[7] * Tev[jj] + C[8] * Tev[jj + 1] + C[9] * Tev[jj + 2];
            acc1[2 * jj + 1] += C[7] * Tod[jj] + C[8] * Tod[jj + 1] + C[9] * Tod[jj + 2];
        }
    }

    float* ob0 = out + ((size_t)bc * 1024 + (size_t)(2 * i)) * 1024 + (size_t)(2 * j0);
    float* ob1 = ob0 + 1024;
#pragma unroll
    for (int t = 0; t < 2 * CW; t += 4) {
        *(float4*)(ob0 + t) = make_float4(acc0[t], acc0[t + 1], acc0[t + 2], acc0[t + 3]);
        *(float4*)(ob1 + t) = make_float4(acc1[t], acc1[t + 1], acc1[t + 2], acc1[t + 3]);
    }
}

extern "C" void kernel_launch(void* const* d_in, const int* in_sizes, int n_in,
                              void* d_out, int out_size) {
    const float* x = (const float*)d_in[0];
    // inputs (metadata order): x, fll, flh, fhl, fhh
    ihaar_setup<<<1, 32>>>((const float*)d_in[1], (const float*)d_in[2],
                           (const float*)d_in[3], (const float*)d_in[4]);
    void* src = nullptr;
    cudaGetSymbolAddress(&src, g_coef_d);
    cudaMemcpyToSymbolAsync(g_coef_c, src, 48 * sizeof(float), 0,
                            cudaMemcpyDeviceToDevice, 0);
    const int total = 48 * 512 * 64;   // (16*3) channels x 512 rows x 64 col-groups
    ihaar_kernel<<<total / 128, 128>>>(x, (float*)d_out);
}